// round 13
// baseline (speedup 1.0000x reference)
#include <cuda_runtime.h>
#include <cuda_fp16.h>
#include <cstdint>
#include <math.h>

#define NB    64
#define NODES 512
#define FDIM  256
#define ALPHA 0.2f
#define NCHUNK 4
#define CB    (NB / NCHUNK)       // 16 batches per chunk

// ---------------- scratch ----------------
__device__ __half g_h16 [NB * NODES * FDIM];
__device__ __half g_att [NB * NODES * NODES];
__device__ __half g_Wh  [NB * NODES * FDIM];
__device__ __half g_W16 [FDIM * FDIM];
__device__ float  g_wa  [2 * FDIM];
__device__ float  g_src [NB * NODES];
__device__ float  g_dst [NB * NODES];

// ---------------- helpers ----------------
__device__ __forceinline__ uint32_t smem_u32(const void* p) {
    uint32_t a;
    asm("{ .reg .u64 t; cvta.to.shared.u64 t, %1; cvt.u32.u64 %0, t; }" : "=r"(a) : "l"(p));
    return a;
}
__device__ __forceinline__ void cp16(uint32_t d, const void* g) {
    asm volatile("cp.async.cg.shared.global [%0], [%1], 16;" :: "r"(d), "l"(g));
}
#define CP_COMMIT() asm volatile("cp.async.commit_group;" ::: "memory")
#define CP_WAIT(n)  asm volatile("cp.async.wait_group %0;" :: "n"(n) : "memory")

#define LDSM4(r, addr)                                                       \
    asm volatile("ldmatrix.sync.aligned.m8n8.x4.shared.b16 {%0,%1,%2,%3}, [%4];" \
        : "=r"((r)[0]), "=r"((r)[1]), "=r"((r)[2]), "=r"((r)[3]) : "r"(addr))
#define LDSM4T(r0, r1, r2, r3, addr)                                         \
    asm volatile("ldmatrix.sync.aligned.m8n8.x4.trans.shared.b16 {%0,%1,%2,%3}, [%4];" \
        : "=r"(r0), "=r"(r1), "=r"(r2), "=r"(r3) : "r"(addr))

__device__ __forceinline__ void mma16816(float* d, const uint32_t* a, const uint32_t* b) {
    asm volatile(
        "mma.sync.aligned.m16n8k16.row.col.f32.f16.f16.f32 "
        "{%0,%1,%2,%3}, {%4,%5,%6,%7}, {%8,%9}, {%0,%1,%2,%3};"
        : "+f"(d[0]), "+f"(d[1]), "+f"(d[2]), "+f"(d[3])
        : "r"(a[0]), "r"(a[1]), "r"(a[2]), "r"(a[3]), "r"(b[0]), "r"(b[1]));
}

#define SWZA(x) ((x) ^ (((x) >> 3) & 0x70))
#define SWZB(x) ((x) ^ (((x) >> 4) & 0x70))

// degree-6 FMA-only exp (ELU epilogue)
__device__ __forceinline__ float fast_exp(float x) {
    x = fmaxf(x, -80.0f);
    float n = rintf(x * 1.442695041f);
    float r = fmaf(n, -0.693359375f, x);
    r = fmaf(n, 2.12194440e-4f, r);
    float p = 1.9875691500E-4f;
    p = fmaf(p, r, 1.3981999507E-3f);
    p = fmaf(p, r, 8.3334519073E-3f);
    p = fmaf(p, r, 4.1665795894E-2f);
    p = fmaf(p, r, 1.6666665459E-1f);
    p = fmaf(p, r, 5.0000001201E-1f);
    float z = fmaf(p * r, r, r) + 1.0f;
    return z * __int_as_float(((int)n + 127) << 23);
}
// degree-4 (softmax weights; fp16 storage dominates error)
__device__ __forceinline__ float fast_exp4(float x) {
    x = fmaxf(x, -80.0f);
    float n = rintf(x * 1.442695041f);
    float r = fmaf(n, -0.693147181f, x);
    float p = 4.1666667e-2f;
    p = fmaf(p, r, 1.6666667e-1f);
    p = fmaf(p, r, 0.5f);
    p = fmaf(p, r, 1.0f);
    p = fmaf(p, r, 1.0f);
    return p * __int_as_float(((int)n + 127) << 23);
}

// ============================================================================
// prep_w: W fp32 -> fp16 + wa1/wa2 projections.
// ============================================================================
__global__ __launch_bounds__(256) void prep_w(const float* __restrict__ W,
                                              const float* __restrict__ a,
                                              __half* __restrict__ W16,
                                              float* __restrict__ wa)
{
    const int b = blockIdx.x, tid = threadIdx.x;
    {
        long i = (long)b * 256 + tid;
        float4 v = ((const float4*)W)[i];
        __half2 h0, h1;
        h0.x = __float2half(v.x); h0.y = __float2half(v.y);
        h1.x = __float2half(v.z); h1.y = __float2half(v.w);
        ((__half2*)W16)[2 * i] = h0; ((__half2*)W16)[2 * i + 1] = h1;
    }
    if (b < 32) {
        const int w = tid >> 5, lane = tid & 31;
        const int k = b * 8 + w;
        const float* row = W + (long)k * FDIM;
        float s1 = 0.f, s2 = 0.f;
        #pragma unroll
        for (int f = lane; f < FDIM; f += 32) {
            float v = row[f];
            s1 = fmaf(v, a[f], s1);
            s2 = fmaf(v, a[FDIM + f], s2);
        }
        #pragma unroll
        for (int o = 16; o; o >>= 1) {
            s1 += __shfl_xor_sync(0xffffffffu, s1, o);
            s2 += __shfl_xor_sync(0xffffffffu, s2, o);
        }
        if (lane == 0) { wa[k] = s1; wa[FDIM + k] = s2; }
    }
}

// ============================================================================
// conv_h: h fp32 -> fp16 + exact fp32 src/dst dots.  (chunk via pointer offset)
// ============================================================================
__global__ __launch_bounds__(256) void conv_h(const float4* __restrict__ h4,
                                              __half* __restrict__ hh,
                                              const float* __restrict__ wa,
                                              float* __restrict__ srcv,
                                              float* __restrict__ dstv)
{
    const int warp = threadIdx.x >> 5;
    const int lane = threadIdx.x & 31;
    const long row = (long)blockIdx.x * 8 + warp;
    const float4* hrow = h4 + row * 64;

    float4 v0 = hrow[2 * lane];
    float4 v1 = hrow[2 * lane + 1];

    __half2 o[4];
    o[0].x = __float2half(v0.x); o[0].y = __float2half(v0.y);
    o[1].x = __float2half(v0.z); o[1].y = __float2half(v0.w);
    o[2].x = __float2half(v1.x); o[2].y = __float2half(v1.y);
    o[3].x = __float2half(v1.z); o[3].y = __float2half(v1.w);
    *(uint4*)(hh + row * FDIM + lane * 8) = *(uint4*)o;

    const float4* w14 = (const float4*)(wa) + lane * 2;
    const float4* w24 = (const float4*)(wa + FDIM) + lane * 2;
    float4 a0 = w14[0], a1v = w14[1], b0 = w24[0], b1 = w24[1];
    float s1 = v0.x * a0.x + v0.y * a0.y + v0.z * a0.z + v0.w * a0.w
             + v1.x * a1v.x + v1.y * a1v.y + v1.z * a1v.z + v1.w * a1v.w;
    float s2 = v0.x * b0.x + v0.y * b0.y + v0.z * b0.z + v0.w * b0.w
             + v1.x * b1.x + v1.y * b1.y + v1.z * b1.z + v1.w * b1.w;
    #pragma unroll
    for (int o2 = 16; o2; o2 >>= 1) {
        s1 += __shfl_xor_sync(0xffffffffu, s1, o2);
        s2 += __shfl_xor_sync(0xffffffffu, s2, o2);
    }
    if (lane == 0) { srcv[row] = s1; dstv[row] = s2; }
}

// ============================================================================
// GEMM1: Wh = h16 @ W16, 1-pass fp16, 2-stage pipeline, 2 CTAs/SM.
// ============================================================================
#define G_STAGE 32768
#define G_SMEM  (2 * G_STAGE)
__global__ __launch_bounds__(256, 2) void gemm1_kernel(
    const __half* __restrict__ A, const __half* __restrict__ B,
    __half* __restrict__ Wh)
{
    extern __shared__ __align__(16) char smem[];
    const uint32_t sb = smem_u32(smem);
    const int tid  = threadIdx.x;
    const int lane = tid & 31;
    const int wid  = tid >> 5;
    const int wm   = wid >> 1;
    const int wn   = wid & 1;
    const int bz   = blockIdx.z;
    const int m0   = blockIdx.y * 128;
    const int n0   = blockIdx.x * 128;

    const __half* Ab = A + (long)bz * NODES * FDIM + (long)m0 * FDIM;
    const __half* Bb = B + n0;

    constexpr int NC = FDIM / 64;

    float acc[2][8][4];
    #pragma unroll
    for (int i = 0; i < 2; i++)
        #pragma unroll
        for (int j = 0; j < 8; j++)
            #pragma unroll
            for (int q = 0; q < 4; q++) acc[i][j][q] = 0.f;

    auto load_chunk = [&](int st, int c) {
        const int k0 = c * 64;
        const uint32_t dA = sb + st * G_STAGE;
        const uint32_t dB = dA + 16384;
        #pragma unroll
        for (int i = 0; i < 4; i++) {
            int idx = tid + i * 256, r = idx >> 3, s = idx & 7;
            cp16(dA + SWZA(r * 128 + s * 16), Ab + (long)r * FDIM + k0 + s * 8);
        }
        #pragma unroll
        for (int i = 0; i < 4; i++) {
            int idx = tid + i * 256, r = idx >> 4, s = idx & 15;
            cp16(dB + SWZB(r * 256 + s * 16), Bb + (long)(k0 + r) * FDIM + s * 8);
        }
        CP_COMMIT();
    };

    const int alr = lane & 15;
    const int alc = lane >> 4;

    load_chunk(0, 0);
    for (int c = 0; c < NC; ++c) {
        const int s = c & 1;
        if (c + 1 < NC) { load_chunk(s ^ 1, c + 1); CP_WAIT(1); }
        else            { CP_WAIT(0); }
        __syncthreads();

        const uint32_t sA = sb + s * G_STAGE;
        const uint32_t sB = sA + 16384;
        #pragma unroll
        for (int kk = 0; kk < 4; kk++) {
            uint32_t a[2][4];
            #pragma unroll
            for (int mt = 0; mt < 2; mt++)
                LDSM4(a[mt], sA + SWZA((wm * 32 + mt * 16 + alr) * 128 + kk * 32 + alc * 16));
            uint32_t b[8][2];
            #pragma unroll
            for (int np = 0; np < 4; np++) {
                uint32_t t0, t1, t2, t3;
                LDSM4T(t0, t1, t2, t3,
                       sB + SWZB((kk * 16 + alr) * 256 + (wn * 64 + np * 16 + alc * 8) * 2));
                b[2 * np][0] = t0; b[2 * np][1] = t1;
                b[2 * np + 1][0] = t2; b[2 * np + 1][1] = t3;
            }
            #pragma unroll
            for (int mt = 0; mt < 2; mt++)
                #pragma unroll
                for (int nt = 0; nt < 8; nt++)
                    mma16816(acc[mt][nt], a[mt], b[nt]);
        }
        __syncthreads();
    }

    const int g  = lane >> 2;
    const int t2 = (lane & 3) * 2;
    __half2* cT = (__half2*)(smem);
    #pragma unroll
    for (int mt = 0; mt < 2; mt++)
        #pragma unroll
        for (int nt = 0; nt < 8; nt++) {
            const int r  = wm * 32 + mt * 16 + g;
            const int cc = wn * 64 + nt * 8 + t2;
            __half2 h01, h23;
            h01.x = __float2half(acc[mt][nt][0]); h01.y = __float2half(acc[mt][nt][1]);
            h23.x = __float2half(acc[mt][nt][2]); h23.y = __float2half(acc[mt][nt][3]);
            cT[(r * 128 + cc) >> 1]       = h01;
            cT[((r + 8) * 128 + cc) >> 1] = h23;
        }
    __syncthreads();
    #pragma unroll
    for (int i = 0; i < 8; i++) {
        int idx = tid + i * 256;
        int r = idx >> 4, ch = idx & 15;
        long gofs = ((long)bz * NODES + m0 + r) * FDIM + n0 + ch * 8;
        *(uint4*)(Wh + gofs) = *(uint4*)(smem + r * 256 + ch * 16);
    }
}

// ============================================================================
// GEMM2: out = elu(att @ Wh), 1-pass fp16, 2-stage pipeline, 2 CTAs/SM.
// ============================================================================
__global__ __launch_bounds__(256, 2) void gemm2_kernel(
    const __half* __restrict__ att, const __half* __restrict__ B,
    float* __restrict__ outp)
{
    extern __shared__ __align__(16) char smem[];
    const uint32_t sb = smem_u32(smem);
    const int tid  = threadIdx.x;
    const int lane = tid & 31;
    const int wid  = tid >> 5;
    const int wm   = wid >> 1;
    const int wn   = wid & 1;
    const int bz   = blockIdx.z;
    const int m0   = blockIdx.y * 128;
    const int n0   = blockIdx.x * 128;

    const __half* Ab = att + (long)bz * NODES * NODES + (long)m0 * NODES;
    const __half* Bb = B + (long)bz * NODES * FDIM + n0;

    constexpr int NC = NODES / 64;

    float acc[2][8][4];
    #pragma unroll
    for (int i = 0; i < 2; i++)
        #pragma unroll
        for (int j = 0; j < 8; j++)
            #pragma unroll
            for (int q = 0; q < 4; q++) acc[i][j][q] = 0.f;

    auto load_chunk = [&](int st, int c) {
        const int k0 = c * 64;
        const uint32_t dA = sb + st * G_STAGE;
        const uint32_t dB = dA + 16384;
        #pragma unroll
        for (int i = 0; i < 4; i++) {
            int idx = tid + i * 256, r = idx >> 3, s = idx & 7;
            cp16(dA + SWZA(r * 128 + s * 16), Ab + (long)r * NODES + k0 + s * 8);
        }
        #pragma unroll
        for (int i = 0; i < 4; i++) {
            int idx = tid + i * 256, r = idx >> 4, s = idx & 15;
            cp16(dB + SWZB(r * 256 + s * 16), Bb + (long)(k0 + r) * FDIM + s * 8);
        }
        CP_COMMIT();
    };

    const int alr = lane & 15;
    const int alc = lane >> 4;

    load_chunk(0, 0);
    for (int c = 0; c < NC; ++c) {
        const int s = c & 1;
        if (c + 1 < NC) { load_chunk(s ^ 1, c + 1); CP_WAIT(1); }
        else            { CP_WAIT(0); }
        __syncthreads();

        const uint32_t sA = sb + s * G_STAGE;
        const uint32_t sB = sA + 16384;
        #pragma unroll
        for (int kk = 0; kk < 4; kk++) {
            uint32_t a[2][4];
            #pragma unroll
            for (int mt = 0; mt < 2; mt++)
                LDSM4(a[mt], sA + SWZA((wm * 32 + mt * 16 + alr) * 128 + kk * 32 + alc * 16));
            uint32_t b[8][2];
            #pragma unroll
            for (int np = 0; np < 4; np++) {
                uint32_t t0, t1, t2, t3;
                LDSM4T(t0, t1, t2, t3,
                       sB + SWZB((kk * 16 + alr) * 256 + (wn * 64 + np * 16 + alc * 8) * 2));
                b[2 * np][0] = t0; b[2 * np][1] = t1;
                b[2 * np + 1][0] = t2; b[2 * np + 1][1] = t3;
            }
            #pragma unroll
            for (int mt = 0; mt < 2; mt++)
                #pragma unroll
                for (int nt = 0; nt < 8; nt++)
                    mma16816(acc[mt][nt], a[mt], b[nt]);
        }
        __syncthreads();
    }

    const int g  = lane >> 2;
    const int t2 = (lane & 3) * 2;
    #pragma unroll
    for (int mt = 0; mt < 2; mt++)
        #pragma unroll
        for (int nt = 0; nt < 8; nt++) {
            const long base = ((long)bz * NODES + m0 + wm * 32 + mt * 16) * FDIM
                            + n0 + wn * 64 + nt * 8 + t2;
            float v0 = acc[mt][nt][0], v1 = acc[mt][nt][1];
            float v2 = acc[mt][nt][2], v3 = acc[mt][nt][3];
            float2 r01, r23;
            r01.x = v0 > 0.f ? v0 : fast_exp(v0) - 1.f;
            r01.y = v1 > 0.f ? v1 : fast_exp(v1) - 1.f;
            r23.x = v2 > 0.f ? v2 : fast_exp(v2) - 1.f;
            r23.y = v3 > 0.f ? v3 : fast_exp(v3) - 1.f;
            *(float2*)(outp + base + (long)g * FDIM)       = r01;
            *(float2*)(outp + base + (long)(g + 8) * FDIM) = r23;
        }
}

// ============================================================================
// Warp-per-row masked softmax (coalesced).  (chunk via pointer offsets)
// ============================================================================
__global__ __launch_bounds__(256) void attn_kernel(const int* __restrict__ adj,
                                                   const float* __restrict__ srcv,
                                                   const float* __restrict__ dstv,
                                                   __half* __restrict__ att)
{
    const int warp = threadIdx.x >> 5;
    const int lane = threadIdx.x & 31;
    const int row  = blockIdx.x * 8 + warp;
    const int bn   = row >> 9;
    const int i    = row & (NODES - 1);

    const float si = srcv[row];
    const int4*   adj4 = (const int4*)(adj + i * NODES);
    const float4* dv   = (const float4*)(dstv + bn * NODES);

    float p[16];
    float sum = 0.f;
    #pragma unroll
    for (int k = 0; k < 4; k++) {
        const int q = k * 32 + lane;
        int4   av = adj4[q];
        float4 d  = dv[q];
        float e0 = si + d.x; e0 = e0 > 0.f ? e0 : ALPHA * e0;
        float e1 = si + d.y; e1 = e1 > 0.f ? e1 : ALPHA * e1;
        float e2 = si + d.z; e2 = e2 > 0.f ? e2 : ALPHA * e2;
        float e3 = si + d.w; e3 = e3 > 0.f ? e3 : ALPHA * e3;
        p[k * 4 + 0] = (av.x > 0) ? fast_exp4(e0) : 0.f;
        p[k * 4 + 1] = (av.y > 0) ? fast_exp4(e1) : 0.f;
        p[k * 4 + 2] = (av.z > 0) ? fast_exp4(e2) : 0.f;
        p[k * 4 + 3] = (av.w > 0) ? fast_exp4(e3) : 0.f;
        sum += p[k * 4 + 0] + p[k * 4 + 1] + p[k * 4 + 2] + p[k * 4 + 3];
    }
    #pragma unroll
    for (int o = 16; o; o >>= 1) sum += __shfl_xor_sync(0xffffffffu, sum, o);
    const float rinv = __frcp_rn(sum);

    __half* arow = att + ((long)bn * NODES + i) * NODES;
    #pragma unroll
    for (int k = 0; k < 4; k++) {
        __half2 h2[2];
        h2[0].x = __float2half(p[k * 4 + 0] * rinv);
        h2[0].y = __float2half(p[k * 4 + 1] * rinv);
        h2[1].x = __float2half(p[k * 4 + 2] * rinv);
        h2[1].y = __float2half(p[k * 4 + 3] * rinv);
        *(uint2*)(arow + k * 128 + lane * 4) = *(uint2*)h2;
    }
}

// ============================================================================
extern "C" void kernel_launch(void* const* d_in, const int* in_sizes, int n_in,
                              void* d_out, int out_size)
{
    const float* h   = (const float*)d_in[0];
    const int*   adj = (const int*)d_in[1];
    const float* W   = (const float*)d_in[2];
    const float* a   = (const float*)d_in[3];
    float* out = (float*)d_out;

    __half *hh, *atp, *w16, *wh;
    float *wa, *srcp, *dstp;
    cudaGetSymbolAddress((void**)&hh,  g_h16);
    cudaGetSymbolAddress((void**)&atp, g_att);
    cudaGetSymbolAddress((void**)&w16, g_W16);
    cudaGetSymbolAddress((void**)&wh,  g_Wh);
    cudaGetSymbolAddress((void**)&wa,  g_wa);
    cudaGetSymbolAddress((void**)&srcp, g_src);
    cudaGetSymbolAddress((void**)&dstp, g_dst);

    static bool init_done = false;
    static cudaStream_t s1, s2;
    static cudaEvent_t evC[NCHUNK], evA[NCHUNK], evG[NCHUNK], evEnd;
    if (!init_done) {
        cudaStreamCreateWithFlags(&s1, cudaStreamNonBlocking);
        cudaStreamCreateWithFlags(&s2, cudaStreamNonBlocking);
        for (int c = 0; c < NCHUNK; c++) {
            cudaEventCreateWithFlags(&evC[c], cudaEventDisableTiming);
            cudaEventCreateWithFlags(&evA[c], cudaEventDisableTiming);
            cudaEventCreateWithFlags(&evG[c], cudaEventDisableTiming);
        }
        cudaEventCreateWithFlags(&evEnd, cudaEventDisableTiming);
        cudaFuncSetAttribute(gemm1_kernel, cudaFuncAttributeMaxDynamicSharedMemorySize, G_SMEM);
        cudaFuncSetAttribute(gemm2_kernel, cudaFuncAttributeMaxDynamicSharedMemorySize, G_SMEM);
        init_done = true;
    }

    // s0 (capture stream): prep, conv chunks, gemm1 chunks
    prep_w<<<64, 256>>>(W, a, w16, wa);

    const dim3 gGrid(FDIM / 128, NODES / 128, CB);
    for (int c = 0; c < NCHUNK; c++) {
        const long rowOfs = (long)c * CB * NODES;            // node rows
        const long hOfs   = rowOfs * FDIM;                   // h / Wh elements
        const long aOfs   = rowOfs * NODES;                  // att elements

        // conv chunk on s0
        conv_h<<<CB * NODES / 8, 256>>>(
            (const float4*)(h + hOfs), hh + hOfs, wa, srcp + rowOfs, dstp + rowOfs);
        cudaEventRecord(evC[c], 0);

        // attn chunk on s1 (needs conv_c)
        cudaStreamWaitEvent(s1, evC[c], 0);
        attn_kernel<<<CB * NODES / 8, 256, 0, s1>>>(
            adj, srcp + rowOfs, dstp + rowOfs, atp + aOfs);
        cudaEventRecord(evA[c], s1);

        // gemm1 chunk on s0
        gemm1_kernel<<<gGrid, 256, G_SMEM>>>(hh + hOfs, w16, wh + hOfs);
        cudaEventRecord(evG[c], 0);

        // gemm2 chunk on s2 (needs attn_c and gemm1_c)
        cudaStreamWaitEvent(s2, evA[c], 0);
        cudaStreamWaitEvent(s2, evG[c], 0);
        gemm2_kernel<<<gGrid, 256, G_SMEM, s2>>>(atp + aOfs, wh + hOfs, out + hOfs);
    }

    // join all side-stream work back into the capture stream
    cudaEventRecord(evEnd, s2);
    cudaStreamWaitEvent(0, evEnd, 0);
}

// round 14
// speedup vs baseline: 1.1956x; 1.1956x over previous
#include <cuda_runtime.h>
#include <cuda_fp16.h>
#include <cstdint>
#include <math.h>

#define NB    64
#define NODES 512
#define FDIM  256
#define ALPHA 0.2f
#define NCHUNK 2
#define CB    (NB / NCHUNK)       // 32 batches per chunk

// ---------------- scratch ----------------
__device__ __half g_h16 [NB * NODES * FDIM];
__device__ __half g_att [NB * NODES * NODES];
__device__ __half g_Wh  [NB * NODES * FDIM];
__device__ __half g_W16 [FDIM * FDIM];
__device__ float  g_wa  [2 * FDIM];
__device__ float  g_src [NB * NODES];
__device__ float  g_dst [NB * NODES];

// ---------------- helpers ----------------
__device__ __forceinline__ uint32_t smem_u32(const void* p) {
    uint32_t a;
    asm("{ .reg .u64 t; cvta.to.shared.u64 t, %1; cvt.u32.u64 %0, t; }" : "=r"(a) : "l"(p));
    return a;
}
__device__ __forceinline__ void cp16(uint32_t d, const void* g) {
    asm volatile("cp.async.cg.shared.global [%0], [%1], 16;" :: "r"(d), "l"(g));
}
#define CP_COMMIT() asm volatile("cp.async.commit_group;" ::: "memory")
#define CP_WAIT(n)  asm volatile("cp.async.wait_group %0;" :: "n"(n) : "memory")

#define LDSM4(r, addr)                                                       \
    asm volatile("ldmatrix.sync.aligned.m8n8.x4.shared.b16 {%0,%1,%2,%3}, [%4];" \
        : "=r"((r)[0]), "=r"((r)[1]), "=r"((r)[2]), "=r"((r)[3]) : "r"(addr))
#define LDSM4T(r0, r1, r2, r3, addr)                                         \
    asm volatile("ldmatrix.sync.aligned.m8n8.x4.trans.shared.b16 {%0,%1,%2,%3}, [%4];" \
        : "=r"(r0), "=r"(r1), "=r"(r2), "=r"(r3) : "r"(addr))

__device__ __forceinline__ void mma16816(float* d, const uint32_t* a, const uint32_t* b) {
    asm volatile(
        "mma.sync.aligned.m16n8k16.row.col.f32.f16.f16.f32 "
        "{%0,%1,%2,%3}, {%4,%5,%6,%7}, {%8,%9}, {%0,%1,%2,%3};"
        : "+f"(d[0]), "+f"(d[1]), "+f"(d[2]), "+f"(d[3])
        : "r"(a[0]), "r"(a[1]), "r"(a[2]), "r"(a[3]), "r"(b[0]), "r"(b[1]));
}

#define SWZA(x) ((x) ^ (((x) >> 3) & 0x70))
#define SWZB(x) ((x) ^ (((x) >> 4) & 0x70))

// degree-6 FMA-only exp (ELU epilogue)
__device__ __forceinline__ float fast_exp(float x) {
    x = fmaxf(x, -80.0f);
    float n = rintf(x * 1.442695041f);
    float r = fmaf(n, -0.693359375f, x);
    r = fmaf(n, 2.12194440e-4f, r);
    float p = 1.9875691500E-4f;
    p = fmaf(p, r, 1.3981999507E-3f);
    p = fmaf(p, r, 8.3334519073E-3f);
    p = fmaf(p, r, 4.1665795894E-2f);
    p = fmaf(p, r, 1.6666665459E-1f);
    p = fmaf(p, r, 5.0000001201E-1f);
    float z = fmaf(p * r, r, r) + 1.0f;
    return z * __int_as_float(((int)n + 127) << 23);
}
// degree-4 (softmax weights; fp16 storage dominates error)
__device__ __forceinline__ float fast_exp4(float x) {
    x = fmaxf(x, -80.0f);
    float n = rintf(x * 1.442695041f);
    float r = fmaf(n, -0.693147181f, x);
    float p = 4.1666667e-2f;
    p = fmaf(p, r, 1.6666667e-1f);
    p = fmaf(p, r, 0.5f);
    p = fmaf(p, r, 1.0f);
    p = fmaf(p, r, 1.0f);
    return p * __int_as_float(((int)n + 127) << 23);
}

// ============================================================================
// prep_w: W fp32 -> fp16 + wa1/wa2 projections.
// ============================================================================
__global__ __launch_bounds__(256) void prep_w(const float* __restrict__ W,
                                              const float* __restrict__ a,
                                              __half* __restrict__ W16,
                                              float* __restrict__ wa)
{
    const int b = blockIdx.x, tid = threadIdx.x;
    {
        long i = (long)b * 256 + tid;
        float4 v = ((const float4*)W)[i];
        __half2 h0, h1;
        h0.x = __float2half(v.x); h0.y = __float2half(v.y);
        h1.x = __float2half(v.z); h1.y = __float2half(v.w);
        ((__half2*)W16)[2 * i] = h0; ((__half2*)W16)[2 * i + 1] = h1;
    }
    if (b < 32) {
        const int w = tid >> 5, lane = tid & 31;
        const int k = b * 8 + w;
        const float* row = W + (long)k * FDIM;
        float s1 = 0.f, s2 = 0.f;
        #pragma unroll
        for (int f = lane; f < FDIM; f += 32) {
            float v = row[f];
            s1 = fmaf(v, a[f], s1);
            s2 = fmaf(v, a[FDIM + f], s2);
        }
        #pragma unroll
        for (int o = 16; o; o >>= 1) {
            s1 += __shfl_xor_sync(0xffffffffu, s1, o);
            s2 += __shfl_xor_sync(0xffffffffu, s2, o);
        }
        if (lane == 0) { wa[k] = s1; wa[FDIM + k] = s2; }
    }
}

// ============================================================================
// conv_h: h fp32 -> fp16 + exact fp32 src/dst dots.
// ============================================================================
__global__ __launch_bounds__(256) void conv_h(const float4* __restrict__ h4,
                                              __half* __restrict__ hh,
                                              const float* __restrict__ wa,
                                              float* __restrict__ srcv,
                                              float* __restrict__ dstv)
{
    const int warp = threadIdx.x >> 5;
    const int lane = threadIdx.x & 31;
    const long row = (long)blockIdx.x * 8 + warp;
    const float4* hrow = h4 + row * 64;

    float4 v0 = hrow[2 * lane];
    float4 v1 = hrow[2 * lane + 1];

    __half2 o[4];
    o[0].x = __float2half(v0.x); o[0].y = __float2half(v0.y);
    o[1].x = __float2half(v0.z); o[1].y = __float2half(v0.w);
    o[2].x = __float2half(v1.x); o[2].y = __float2half(v1.y);
    o[3].x = __float2half(v1.z); o[3].y = __float2half(v1.w);
    *(uint4*)(hh + row * FDIM + lane * 8) = *(uint4*)o;

    const float4* w14 = (const float4*)(wa) + lane * 2;
    const float4* w24 = (const float4*)(wa + FDIM) + lane * 2;
    float4 a0 = w14[0], a1v = w14[1], b0 = w24[0], b1 = w24[1];
    float s1 = v0.x * a0.x + v0.y * a0.y + v0.z * a0.z + v0.w * a0.w
             + v1.x * a1v.x + v1.y * a1v.y + v1.z * a1v.z + v1.w * a1v.w;
    float s2 = v0.x * b0.x + v0.y * b0.y + v0.z * b0.z + v0.w * b0.w
             + v1.x * b1.x + v1.y * b1.y + v1.z * b1.z + v1.w * b1.w;
    #pragma unroll
    for (int o2 = 16; o2; o2 >>= 1) {
        s1 += __shfl_xor_sync(0xffffffffu, s1, o2);
        s2 += __shfl_xor_sync(0xffffffffu, s2, o2);
    }
    if (lane == 0) { srcv[row] = s1; dstv[row] = s2; }
}

// ============================================================================
// GEMM1: Wh = h16 @ W16, 1-pass fp16, 2-stage pipeline, 2 CTAs/SM.
// ============================================================================
#define G_STAGE 32768
#define G_SMEM  (2 * G_STAGE)
__global__ __launch_bounds__(256, 2) void gemm1_kernel(
    const __half* __restrict__ A, const __half* __restrict__ B,
    __half* __restrict__ Wh)
{
    extern __shared__ __align__(16) char smem[];
    const uint32_t sb = smem_u32(smem);
    const int tid  = threadIdx.x;
    const int lane = tid & 31;
    const int wid  = tid >> 5;
    const int wm   = wid >> 1;
    const int wn   = wid & 1;
    const int bz   = blockIdx.z;
    const int m0   = blockIdx.y * 128;
    const int n0   = blockIdx.x * 128;

    const __half* Ab = A + (long)bz * NODES * FDIM + (long)m0 * FDIM;
    const __half* Bb = B + n0;

    constexpr int NC = FDIM / 64;

    float acc[2][8][4];
    #pragma unroll
    for (int i = 0; i < 2; i++)
        #pragma unroll
        for (int j = 0; j < 8; j++)
            #pragma unroll
            for (int q = 0; q < 4; q++) acc[i][j][q] = 0.f;

    auto load_chunk = [&](int st, int c) {
        const int k0 = c * 64;
        const uint32_t dA = sb + st * G_STAGE;
        const uint32_t dB = dA + 16384;
        #pragma unroll
        for (int i = 0; i < 4; i++) {
            int idx = tid + i * 256, r = idx >> 3, s = idx & 7;
            cp16(dA + SWZA(r * 128 + s * 16), Ab + (long)r * FDIM + k0 + s * 8);
        }
        #pragma unroll
        for (int i = 0; i < 4; i++) {
            int idx = tid + i * 256, r = idx >> 4, s = idx & 15;
            cp16(dB + SWZB(r * 256 + s * 16), Bb + (long)(k0 + r) * FDIM + s * 8);
        }
        CP_COMMIT();
    };

    const int alr = lane & 15;
    const int alc = lane >> 4;

    load_chunk(0, 0);
    for (int c = 0; c < NC; ++c) {
        const int s = c & 1;
        if (c + 1 < NC) { load_chunk(s ^ 1, c + 1); CP_WAIT(1); }
        else            { CP_WAIT(0); }
        __syncthreads();

        const uint32_t sA = sb + s * G_STAGE;
        const uint32_t sB = sA + 16384;
        #pragma unroll
        for (int kk = 0; kk < 4; kk++) {
            uint32_t a[2][4];
            #pragma unroll
            for (int mt = 0; mt < 2; mt++)
                LDSM4(a[mt], sA + SWZA((wm * 32 + mt * 16 + alr) * 128 + kk * 32 + alc * 16));
            uint32_t b[8][2];
            #pragma unroll
            for (int np = 0; np < 4; np++) {
                uint32_t t0, t1, t2, t3;
                LDSM4T(t0, t1, t2, t3,
                       sB + SWZB((kk * 16 + alr) * 256 + (wn * 64 + np * 16 + alc * 8) * 2));
                b[2 * np][0] = t0; b[2 * np][1] = t1;
                b[2 * np + 1][0] = t2; b[2 * np + 1][1] = t3;
            }
            #pragma unroll
            for (int mt = 0; mt < 2; mt++)
                #pragma unroll
                for (int nt = 0; nt < 8; nt++)
                    mma16816(acc[mt][nt], a[mt], b[nt]);
        }
        __syncthreads();
    }

    const int g  = lane >> 2;
    const int t2 = (lane & 3) * 2;
    __half2* cT = (__half2*)(smem);
    #pragma unroll
    for (int mt = 0; mt < 2; mt++)
        #pragma unroll
        for (int nt = 0; nt < 8; nt++) {
            const int r  = wm * 32 + mt * 16 + g;
            const int cc = wn * 64 + nt * 8 + t2;
            __half2 h01, h23;
            h01.x = __float2half(acc[mt][nt][0]); h01.y = __float2half(acc[mt][nt][1]);
            h23.x = __float2half(acc[mt][nt][2]); h23.y = __float2half(acc[mt][nt][3]);
            cT[(r * 128 + cc) >> 1]       = h01;
            cT[((r + 8) * 128 + cc) >> 1] = h23;
        }
    __syncthreads();
    #pragma unroll
    for (int i = 0; i < 8; i++) {
        int idx = tid + i * 256;
        int r = idx >> 4, ch = idx & 15;
        long gofs = ((long)bz * NODES + m0 + r) * FDIM + n0 + ch * 8;
        *(uint4*)(Wh + gofs) = *(uint4*)(smem + r * 256 + ch * 16);
    }
}

// ============================================================================
// GEMM2: out = elu(att @ Wh), 1-pass fp16, 2-stage pipeline, 2 CTAs/SM.
// ============================================================================
__global__ __launch_bounds__(256, 2) void gemm2_kernel(
    const __half* __restrict__ att, const __half* __restrict__ B,
    float* __restrict__ outp)
{
    extern __shared__ __align__(16) char smem[];
    const uint32_t sb = smem_u32(smem);
    const int tid  = threadIdx.x;
    const int lane = tid & 31;
    const int wid  = tid >> 5;
    const int wm   = wid >> 1;
    const int wn   = wid & 1;
    const int bz   = blockIdx.z;
    const int m0   = blockIdx.y * 128;
    const int n0   = blockIdx.x * 128;

    const __half* Ab = att + (long)bz * NODES * NODES + (long)m0 * NODES;
    const __half* Bb = B + (long)bz * NODES * FDIM + n0;

    constexpr int NC = NODES / 64;

    float acc[2][8][4];
    #pragma unroll
    for (int i = 0; i < 2; i++)
        #pragma unroll
        for (int j = 0; j < 8; j++)
            #pragma unroll
            for (int q = 0; q < 4; q++) acc[i][j][q] = 0.f;

    auto load_chunk = [&](int st, int c) {
        const int k0 = c * 64;
        const uint32_t dA = sb + st * G_STAGE;
        const uint32_t dB = dA + 16384;
        #pragma unroll
        for (int i = 0; i < 4; i++) {
            int idx = tid + i * 256, r = idx >> 3, s = idx & 7;
            cp16(dA + SWZA(r * 128 + s * 16), Ab + (long)r * NODES + k0 + s * 8);
        }
        #pragma unroll
        for (int i = 0; i < 4; i++) {
            int idx = tid + i * 256, r = idx >> 4, s = idx & 15;
            cp16(dB + SWZB(r * 256 + s * 16), Bb + (long)(k0 + r) * FDIM + s * 8);
        }
        CP_COMMIT();
    };

    const int alr = lane & 15;
    const int alc = lane >> 4;

    load_chunk(0, 0);
    for (int c = 0; c < NC; ++c) {
        const int s = c & 1;
        if (c + 1 < NC) { load_chunk(s ^ 1, c + 1); CP_WAIT(1); }
        else            { CP_WAIT(0); }
        __syncthreads();

        const uint32_t sA = sb + s * G_STAGE;
        const uint32_t sB = sA + 16384;
        #pragma unroll
        for (int kk = 0; kk < 4; kk++) {
            uint32_t a[2][4];
            #pragma unroll
            for (int mt = 0; mt < 2; mt++)
                LDSM4(a[mt], sA + SWZA((wm * 32 + mt * 16 + alr) * 128 + kk * 32 + alc * 16));
            uint32_t b[8][2];
            #pragma unroll
            for (int np = 0; np < 4; np++) {
                uint32_t t0, t1, t2, t3;
                LDSM4T(t0, t1, t2, t3,
                       sB + SWZB((kk * 16 + alr) * 256 + (wn * 64 + np * 16 + alc * 8) * 2));
                b[2 * np][0] = t0; b[2 * np][1] = t1;
                b[2 * np + 1][0] = t2; b[2 * np + 1][1] = t3;
            }
            #pragma unroll
            for (int mt = 0; mt < 2; mt++)
                #pragma unroll
                for (int nt = 0; nt < 8; nt++)
                    mma16816(acc[mt][nt], a[mt], b[nt]);
        }
        __syncthreads();
    }

    const int g  = lane >> 2;
    const int t2 = (lane & 3) * 2;
    #pragma unroll
    for (int mt = 0; mt < 2; mt++)
        #pragma unroll
        for (int nt = 0; nt < 8; nt++) {
            const long base = ((long)bz * NODES + m0 + wm * 32 + mt * 16) * FDIM
                            + n0 + wn * 64 + nt * 8 + t2;
            float v0 = acc[mt][nt][0], v1 = acc[mt][nt][1];
            float v2 = acc[mt][nt][2], v3 = acc[mt][nt][3];
            float2 r01, r23;
            r01.x = v0 > 0.f ? v0 : fast_exp(v0) - 1.f;
            r01.y = v1 > 0.f ? v1 : fast_exp(v1) - 1.f;
            r23.x = v2 > 0.f ? v2 : fast_exp(v2) - 1.f;
            r23.y = v3 > 0.f ? v3 : fast_exp(v3) - 1.f;
            *(float2*)(outp + base + (long)g * FDIM)       = r01;
            *(float2*)(outp + base + (long)(g + 8) * FDIM) = r23;
        }
}

// ============================================================================
// Warp-per-row masked softmax (coalesced).
// ============================================================================
__global__ __launch_bounds__(256) void attn_kernel(const int* __restrict__ adj,
                                                   const float* __restrict__ srcv,
                                                   const float* __restrict__ dstv,
                                                   __half* __restrict__ att)
{
    const int warp = threadIdx.x >> 5;
    const int lane = threadIdx.x & 31;
    const int row  = blockIdx.x * 8 + warp;
    const int bn   = row >> 9;
    const int i    = row & (NODES - 1);

    const float si = srcv[row];
    const int4*   adj4 = (const int4*)(adj + i * NODES);
    const float4* dv   = (const float4*)(dstv + bn * NODES);

    float p[16];
    float sum = 0.f;
    #pragma unroll
    for (int k = 0; k < 4; k++) {
        const int q = k * 32 + lane;
        int4   av = adj4[q];
        float4 d  = dv[q];
        float e0 = si + d.x; e0 = e0 > 0.f ? e0 : ALPHA * e0;
        float e1 = si + d.y; e1 = e1 > 0.f ? e1 : ALPHA * e1;
        float e2 = si + d.z; e2 = e2 > 0.f ? e2 : ALPHA * e2;
        float e3 = si + d.w; e3 = e3 > 0.f ? e3 : ALPHA * e3;
        p[k * 4 + 0] = (av.x > 0) ? fast_exp4(e0) : 0.f;
        p[k * 4 + 1] = (av.y > 0) ? fast_exp4(e1) : 0.f;
        p[k * 4 + 2] = (av.z > 0) ? fast_exp4(e2) : 0.f;
        p[k * 4 + 3] = (av.w > 0) ? fast_exp4(e3) : 0.f;
        sum += p[k * 4 + 0] + p[k * 4 + 1] + p[k * 4 + 2] + p[k * 4 + 3];
    }
    #pragma unroll
    for (int o = 16; o; o >>= 1) sum += __shfl_xor_sync(0xffffffffu, sum, o);
    const float rinv = __frcp_rn(sum);

    __half* arow = att + ((long)bn * NODES + i) * NODES;
    #pragma unroll
    for (int k = 0; k < 4; k++) {
        __half2 h2[2];
        h2[0].x = __float2half(p[k * 4 + 0] * rinv);
        h2[0].y = __float2half(p[k * 4 + 1] * rinv);
        h2[1].x = __float2half(p[k * 4 + 2] * rinv);
        h2[1].y = __float2half(p[k * 4 + 3] * rinv);
        *(uint2*)(arow + k * 128 + lane * 4) = *(uint2*)h2;
    }
}

// ============================================================================
extern "C" void kernel_launch(void* const* d_in, const int* in_sizes, int n_in,
                              void* d_out, int out_size)
{
    const float* h   = (const float*)d_in[0];
    const int*   adj = (const int*)d_in[1];
    const float* W   = (const float*)d_in[2];
    const float* a   = (const float*)d_in[3];
    float* out = (float*)d_out;

    __half *hh, *atp, *w16, *wh;
    float *wa, *srcp, *dstp;
    cudaGetSymbolAddress((void**)&hh,  g_h16);
    cudaGetSymbolAddress((void**)&atp, g_att);
    cudaGetSymbolAddress((void**)&w16, g_W16);
    cudaGetSymbolAddress((void**)&wh,  g_Wh);
    cudaGetSymbolAddress((void**)&wa,  g_wa);
    cudaGetSymbolAddress((void**)&srcp, g_src);
    cudaGetSymbolAddress((void**)&dstp, g_dst);

    static bool init_done = false;
    static cudaStream_t s1, s2;
    static cudaEvent_t evConv, evA[NCHUNK], evG[NCHUNK], evEnd;
    if (!init_done) {
        cudaStreamCreateWithFlags(&s1, cudaStreamNonBlocking);
        cudaStreamCreateWithFlags(&s2, cudaStreamNonBlocking);
        cudaEventCreateWithFlags(&evConv, cudaEventDisableTiming);
        for (int c = 0; c < NCHUNK; c++) {
            cudaEventCreateWithFlags(&evA[c], cudaEventDisableTiming);
            cudaEventCreateWithFlags(&evG[c], cudaEventDisableTiming);
        }
        cudaEventCreateWithFlags(&evEnd, cudaEventDisableTiming);
        cudaFuncSetAttribute(gemm1_kernel, cudaFuncAttributeMaxDynamicSharedMemorySize, G_SMEM);
        cudaFuncSetAttribute(gemm2_kernel, cudaFuncAttributeMaxDynamicSharedMemorySize, G_SMEM);
        init_done = true;
    }

    // s0 (capture stream): prep + full conv
    prep_w<<<64, 256>>>(W, a, w16, wa);
    conv_h<<<NB * NODES / 8, 256>>>((const float4*)h, hh, wa, srcp, dstp);
    cudaEventRecord(evConv, 0);
    cudaStreamWaitEvent(s1, evConv, 0);

    const dim3 gGrid(FDIM / 128, NODES / 128, CB);
    for (int c = 0; c < NCHUNK; c++) {
        const long rowOfs = (long)c * CB * NODES;
        const long hOfs   = rowOfs * FDIM;
        const long aOfs   = rowOfs * NODES;

        // attn chunk on s1
        attn_kernel<<<CB * NODES / 8, 256, 0, s1>>>(
            adj, srcp + rowOfs, dstp + rowOfs, atp + aOfs);
        cudaEventRecord(evA[c], s1);

        // gemm1 chunk on s0
        gemm1_kernel<<<gGrid, 256, G_SMEM>>>(hh + hOfs, w16, wh + hOfs);
        cudaEventRecord(evG[c], 0);

        // gemm2 chunk on s2 (needs attn_c + gemm1_c)
        cudaStreamWaitEvent(s2, evA[c], 0);
        cudaStreamWaitEvent(s2, evG[c], 0);
        gemm2_kernel<<<gGrid, 256, G_SMEM, s2>>>(atp + aOfs, wh + hOfs, out + hOfs);
    }

    cudaEventRecord(evEnd, s2);
    cudaStreamWaitEvent(0, evEnd, 0);
}

// round 15
// speedup vs baseline: 1.2554x; 1.0500x over previous
#include <cuda_runtime.h>
#include <cuda_fp16.h>
#include <cstdint>
#include <math.h>

#define NB    64
#define NODES 512
#define FDIM  256
#define ALPHA 0.2f

// ---------------- scratch ----------------
__device__ __half g_h16 [NB * NODES * FDIM];
__device__ __half g_att [NB * NODES * NODES];
__device__ __half g_Wh  [NB * NODES * FDIM];
__device__ __half g_W16 [FDIM * FDIM];
__device__ float  g_wa  [2 * FDIM];
__device__ float  g_src [NB * NODES];
__device__ float  g_dst [NB * NODES];

// ---------------- helpers ----------------
__device__ __forceinline__ uint32_t smem_u32(const void* p) {
    uint32_t a;
    asm("{ .reg .u64 t; cvta.to.shared.u64 t, %1; cvt.u32.u64 %0, t; }" : "=r"(a) : "l"(p));
    return a;
}
__device__ __forceinline__ void cp16(uint32_t d, const void* g) {
    asm volatile("cp.async.cg.shared.global [%0], [%1], 16;" :: "r"(d), "l"(g));
}
#define CP_COMMIT() asm volatile("cp.async.commit_group;" ::: "memory")
#define CP_WAIT(n)  asm volatile("cp.async.wait_group %0;" :: "n"(n) : "memory")

#define LDSM4(r, addr)                                                       \
    asm volatile("ldmatrix.sync.aligned.m8n8.x4.shared.b16 {%0,%1,%2,%3}, [%4];" \
        : "=r"((r)[0]), "=r"((r)[1]), "=r"((r)[2]), "=r"((r)[3]) : "r"(addr))
#define LDSM4T(r0, r1, r2, r3, addr)                                         \
    asm volatile("ldmatrix.sync.aligned.m8n8.x4.trans.shared.b16 {%0,%1,%2,%3}, [%4];" \
        : "=r"(r0), "=r"(r1), "=r"(r2), "=r"(r3) : "r"(addr))

__device__ __forceinline__ void mma16816(float* d, const uint32_t* a, const uint32_t* b) {
    asm volatile(
        "mma.sync.aligned.m16n8k16.row.col.f32.f16.f16.f32 "
        "{%0,%1,%2,%3}, {%4,%5,%6,%7}, {%8,%9}, {%0,%1,%2,%3};"
        : "+f"(d[0]), "+f"(d[1]), "+f"(d[2]), "+f"(d[3])
        : "r"(a[0]), "r"(a[1]), "r"(a[2]), "r"(a[3]), "r"(b[0]), "r"(b[1]));
}

// all tiles now have 128B rows
#define SWZ(x) ((x) ^ (((x) >> 3) & 0x70))

// degree-6 FMA-only exp (ELU epilogue)
__device__ __forceinline__ float fast_exp(float x) {
    x = fmaxf(x, -80.0f);
    float n = rintf(x * 1.442695041f);
    float r = fmaf(n, -0.693359375f, x);
    r = fmaf(n, 2.12194440e-4f, r);
    float p = 1.9875691500E-4f;
    p = fmaf(p, r, 1.3981999507E-3f);
    p = fmaf(p, r, 8.3334519073E-3f);
    p = fmaf(p, r, 4.1665795894E-2f);
    p = fmaf(p, r, 1.6666665459E-1f);
    p = fmaf(p, r, 5.0000001201E-1f);
    float z = fmaf(p * r, r, r) + 1.0f;
    return z * __int_as_float(((int)n + 127) << 23);
}
// degree-4 (softmax weights)
__device__ __forceinline__ float fast_exp4(float x) {
    x = fmaxf(x, -80.0f);
    float n = rintf(x * 1.442695041f);
    float r = fmaf(n, -0.693147181f, x);
    float p = 4.1666667e-2f;
    p = fmaf(p, r, 1.6666667e-1f);
    p = fmaf(p, r, 0.5f);
    p = fmaf(p, r, 1.0f);
    p = fmaf(p, r, 1.0f);
    return p * __int_as_float(((int)n + 127) << 23);
}

// ============================================================================
// prep_w: W fp32 -> fp16 + wa1/wa2 projections.
// ============================================================================
__global__ __launch_bounds__(256) void prep_w(const float* __restrict__ W,
                                              const float* __restrict__ a,
                                              __half* __restrict__ W16,
                                              float* __restrict__ wa)
{
    const int b = blockIdx.x, tid = threadIdx.x;
    {
        long i = (long)b * 256 + tid;
        float4 v = ((const float4*)W)[i];
        __half2 h0, h1;
        h0.x = __float2half(v.x); h0.y = __float2half(v.y);
        h1.x = __float2half(v.z); h1.y = __float2half(v.w);
        ((__half2*)W16)[2 * i] = h0; ((__half2*)W16)[2 * i + 1] = h1;
    }
    if (b < 32) {
        const int w = tid >> 5, lane = tid & 31;
        const int k = b * 8 + w;
        const float* row = W + (long)k * FDIM;
        float s1 = 0.f, s2 = 0.f;
        #pragma unroll
        for (int f = lane; f < FDIM; f += 32) {
            float v = row[f];
            s1 = fmaf(v, a[f], s1);
            s2 = fmaf(v, a[FDIM + f], s2);
        }
        #pragma unroll
        for (int o = 16; o; o >>= 1) {
            s1 += __shfl_xor_sync(0xffffffffu, s1, o);
            s2 += __shfl_xor_sync(0xffffffffu, s2, o);
        }
        if (lane == 0) { wa[k] = s1; wa[FDIM + k] = s2; }
    }
}

// ============================================================================
// conv_h: h fp32 -> fp16 + exact fp32 src/dst dots.
// ============================================================================
__global__ __launch_bounds__(256) void conv_h(const float4* __restrict__ h4,
                                              __half* __restrict__ hh,
                                              const float* __restrict__ wa,
                                              float* __restrict__ srcv,
                                              float* __restrict__ dstv)
{
    const int warp = threadIdx.x >> 5;
    const int lane = threadIdx.x & 31;
    const long row = (long)blockIdx.x * 8 + warp;
    const float4* hrow = h4 + row * 64;

    float4 v0 = hrow[2 * lane];
    float4 v1 = hrow[2 * lane + 1];

    __half2 o[4];
    o[0].x = __float2half(v0.x); o[0].y = __float2half(v0.y);
    o[1].x = __float2half(v0.z); o[1].y = __float2half(v0.w);
    o[2].x = __float2half(v1.x); o[2].y = __float2half(v1.y);
    o[3].x = __float2half(v1.z); o[3].y = __float2half(v1.w);
    *(uint4*)(hh + row * FDIM + lane * 8) = *(uint4*)o;

    const float4* w14 = (const float4*)(wa) + lane * 2;
    const float4* w24 = (const float4*)(wa + FDIM) + lane * 2;
    float4 a0 = w14[0], a1v = w14[1], b0 = w24[0], b1 = w24[1];
    float s1 = v0.x * a0.x + v0.y * a0.y + v0.z * a0.z + v0.w * a0.w
             + v1.x * a1v.x + v1.y * a1v.y + v1.z * a1v.z + v1.w * a1v.w;
    float s2 = v0.x * b0.x + v0.y * b0.y + v0.z * b0.z + v0.w * b0.w
             + v1.x * b1.x + v1.y * b1.y + v1.z * b1.z + v1.w * b1.w;
    #pragma unroll
    for (int o2 = 16; o2; o2 >>= 1) {
        s1 += __shfl_xor_sync(0xffffffffu, s1, o2);
        s2 += __shfl_xor_sync(0xffffffffu, s2, o2);
    }
    if (lane == 0) { srcv[row] = s1; dstv[row] = s2; }
}

// ============================================================================
// GEMM core: block tile 128m x 64n, warp tile 32x32, 8 warps, 3 CTAs/SM.
// Stage = A 16KB + B 8KB = 24KB; 2 stages.
// ============================================================================
#define G_STAGE 24576
#define G_SMEM  (2 * G_STAGE)

// GEMM1: Wh = h16 @ W16  (A stride FDIM, B unbatched, fp16 out)
__global__ __launch_bounds__(256, 3) void gemm1_kernel(
    const __half* __restrict__ A, const __half* __restrict__ B,
    __half* __restrict__ Wh)
{
    extern __shared__ __align__(16) char smem[];
    const uint32_t sb = smem_u32(smem);
    const int tid  = threadIdx.x;
    const int lane = tid & 31;
    const int wid  = tid >> 5;
    const int wm   = wid >> 1;          // 0..3 (32 rows each)
    const int wn   = wid & 1;           // 0..1 (32 cols each)
    const int bz   = blockIdx.z;
    const int m0   = blockIdx.y * 128;
    const int n0   = blockIdx.x * 64;

    const __half* Ab = A + (long)bz * NODES * FDIM + (long)m0 * FDIM;
    const __half* Bb = B + n0;

    constexpr int NC = FDIM / 64;       // 4

    float acc[2][4][4];
    #pragma unroll
    for (int i = 0; i < 2; i++)
        #pragma unroll
        for (int j = 0; j < 4; j++)
            #pragma unroll
            for (int q = 0; q < 4; q++) acc[i][j][q] = 0.f;

    auto load_chunk = [&](int st, int c) {
        const int k0 = c * 64;
        const uint32_t dA = sb + st * G_STAGE;
        const uint32_t dB = dA + 16384;
        #pragma unroll
        for (int i = 0; i < 4; i++) {          // A: 128 x 64 halves
            int idx = tid + i * 256, r = idx >> 3, s = idx & 7;
            cp16(dA + SWZ(r * 128 + s * 16), Ab + (long)r * FDIM + k0 + s * 8);
        }
        #pragma unroll
        for (int i = 0; i < 2; i++) {          // B: 64 x 64 halves
            int idx = tid + i * 256, r = idx >> 3, s = idx & 7;
            cp16(dB + SWZ(r * 128 + s * 16), Bb + (long)(k0 + r) * FDIM + s * 8);
        }
        CP_COMMIT();
    };

    const int alr = lane & 15;
    const int alc = lane >> 4;

    load_chunk(0, 0);
    for (int c = 0; c < NC; ++c) {
        const int s = c & 1;
        if (c + 1 < NC) { load_chunk(s ^ 1, c + 1); CP_WAIT(1); }
        else            { CP_WAIT(0); }
        __syncthreads();

        const uint32_t sA = sb + s * G_STAGE;
        const uint32_t sB = sA + 16384;
        #pragma unroll
        for (int kk = 0; kk < 4; kk++) {
            uint32_t a[2][4];
            #pragma unroll
            for (int mt = 0; mt < 2; mt++)
                LDSM4(a[mt], sA + SWZ((wm * 32 + mt * 16 + alr) * 128 + kk * 32 + alc * 16));
            uint32_t b[4][2];
            #pragma unroll
            for (int np = 0; np < 2; np++) {
                uint32_t t0, t1, t2, t3;
                LDSM4T(t0, t1, t2, t3,
                       sB + SWZ((kk * 16 + alr) * 128 + (wn * 32 + np * 16 + alc * 8) * 2));
                b[2 * np][0] = t0; b[2 * np][1] = t1;
                b[2 * np + 1][0] = t2; b[2 * np + 1][1] = t3;
            }
            #pragma unroll
            for (int mt = 0; mt < 2; mt++)
                #pragma unroll
                for (int nt = 0; nt < 4; nt++)
                    mma16816(acc[mt][nt], a[mt], b[nt]);
        }
        __syncthreads();
    }

    // epilogue: stage fp16 tile (128 x 64 = 16KB), then coalesced writes
    const int g  = lane >> 2;
    const int t2 = (lane & 3) * 2;
    __half2* cT = (__half2*)(smem);
    #pragma unroll
    for (int mt = 0; mt < 2; mt++)
        #pragma unroll
        for (int nt = 0; nt < 4; nt++) {
            const int r  = wm * 32 + mt * 16 + g;
            const int cc = wn * 32 + nt * 8 + t2;
            __half2 h01, h23;
            h01.x = __float2half(acc[mt][nt][0]); h01.y = __float2half(acc[mt][nt][1]);
            h23.x = __float2half(acc[mt][nt][2]); h23.y = __float2half(acc[mt][nt][3]);
            cT[(r * 64 + cc) >> 1]       = h01;
            cT[((r + 8) * 64 + cc) >> 1] = h23;
        }
    __syncthreads();
    #pragma unroll
    for (int i = 0; i < 4; i++) {
        int idx = tid + i * 256;            // 1024 uint4s
        int r = idx >> 3, ch = idx & 7;
        long gofs = ((long)bz * NODES + m0 + r) * FDIM + n0 + ch * 8;
        *(uint4*)(Wh + gofs) = *(uint4*)(smem + r * 128 + ch * 16);
    }
}

// GEMM2: out = elu(att @ Wh)  (A stride NODES, B batched, fp32 out)
__global__ __launch_bounds__(256, 3) void gemm2_kernel(
    const __half* __restrict__ att, const __half* __restrict__ B,
    float* __restrict__ outp)
{
    extern __shared__ __align__(16) char smem[];
    const uint32_t sb = smem_u32(smem);
    const int tid  = threadIdx.x;
    const int lane = tid & 31;
    const int wid  = tid >> 5;
    const int wm   = wid >> 1;
    const int wn   = wid & 1;
    const int bz   = blockIdx.z;
    const int m0   = blockIdx.y * 128;
    const int n0   = blockIdx.x * 64;

    const __half* Ab = att + (long)bz * NODES * NODES + (long)m0 * NODES;
    const __half* Bb = B + (long)bz * NODES * FDIM + n0;

    constexpr int NC = NODES / 64;      // 8

    float acc[2][4][4];
    #pragma unroll
    for (int i = 0; i < 2; i++)
        #pragma unroll
        for (int j = 0; j < 4; j++)
            #pragma unroll
            for (int q = 0; q < 4; q++) acc[i][j][q] = 0.f;

    auto load_chunk = [&](int st, int c) {
        const int k0 = c * 64;
        const uint32_t dA = sb + st * G_STAGE;
        const uint32_t dB = dA + 16384;
        #pragma unroll
        for (int i = 0; i < 4; i++) {
            int idx = tid + i * 256, r = idx >> 3, s = idx & 7;
            cp16(dA + SWZ(r * 128 + s * 16), Ab + (long)r * NODES + k0 + s * 8);
        }
        #pragma unroll
        for (int i = 0; i < 2; i++) {
            int idx = tid + i * 256, r = idx >> 3, s = idx & 7;
            cp16(dB + SWZ(r * 128 + s * 16), Bb + (long)(k0 + r) * FDIM + s * 8);
        }
        CP_COMMIT();
    };

    const int alr = lane & 15;
    const int alc = lane >> 4;

    load_chunk(0, 0);
    for (int c = 0; c < NC; ++c) {
        const int s = c & 1;
        if (c + 1 < NC) { load_chunk(s ^ 1, c + 1); CP_WAIT(1); }
        else            { CP_WAIT(0); }
        __syncthreads();

        const uint32_t sA = sb + s * G_STAGE;
        const uint32_t sB = sA + 16384;
        #pragma unroll
        for (int kk = 0; kk < 4; kk++) {
            uint32_t a[2][4];
            #pragma unroll
            for (int mt = 0; mt < 2; mt++)
                LDSM4(a[mt], sA + SWZ((wm * 32 + mt * 16 + alr) * 128 + kk * 32 + alc * 16));
            uint32_t b[4][2];
            #pragma unroll
            for (int np = 0; np < 2; np++) {
                uint32_t t0, t1, t2, t3;
                LDSM4T(t0, t1, t2, t3,
                       sB + SWZ((kk * 16 + alr) * 128 + (wn * 32 + np * 16 + alc * 8) * 2));
                b[2 * np][0] = t0; b[2 * np][1] = t1;
                b[2 * np + 1][0] = t2; b[2 * np + 1][1] = t3;
            }
            #pragma unroll
            for (int mt = 0; mt < 2; mt++)
                #pragma unroll
                for (int nt = 0; nt < 4; nt++)
                    mma16816(acc[mt][nt], a[mt], b[nt]);
        }
        __syncthreads();
    }

    const int g  = lane >> 2;
    const int t2 = (lane & 3) * 2;
    #pragma unroll
    for (int mt = 0; mt < 2; mt++)
        #pragma unroll
        for (int nt = 0; nt < 4; nt++) {
            const long base = ((long)bz * NODES + m0 + wm * 32 + mt * 16) * FDIM
                            + n0 + wn * 32 + nt * 8 + t2;
            float v0 = acc[mt][nt][0], v1 = acc[mt][nt][1];
            float v2 = acc[mt][nt][2], v3 = acc[mt][nt][3];
            float2 r01, r23;
            r01.x = v0 > 0.f ? v0 : fast_exp(v0) - 1.f;
            r01.y = v1 > 0.f ? v1 : fast_exp(v1) - 1.f;
            r23.x = v2 > 0.f ? v2 : fast_exp(v2) - 1.f;
            r23.y = v3 > 0.f ? v3 : fast_exp(v3) - 1.f;
            *(float2*)(outp + base + (long)g * FDIM)       = r01;
            *(float2*)(outp + base + (long)(g + 8) * FDIM) = r23;
        }
}

// ============================================================================
// Warp-per-row masked softmax (coalesced).
// ============================================================================
__global__ __launch_bounds__(256) void attn_kernel(const int* __restrict__ adj,
                                                   const float* __restrict__ srcv,
                                                   const float* __restrict__ dstv,
                                                   __half* __restrict__ att)
{
    const int warp = threadIdx.x >> 5;
    const int lane = threadIdx.x & 31;
    const int row  = blockIdx.x * 8 + warp;
    const int bn   = row >> 9;
    const int i    = row & (NODES - 1);

    const float si = srcv[row];
    const int4*   adj4 = (const int4*)(adj + i * NODES);
    const float4* dv   = (const float4*)(dstv + bn * NODES);

    float p[16];
    float sum = 0.f;
    #pragma unroll
    for (int k = 0; k < 4; k++) {
        const int q = k * 32 + lane;
        int4   av = adj4[q];
        float4 d  = dv[q];
        float e0 = si + d.x; e0 = e0 > 0.f ? e0 : ALPHA * e0;
        float e1 = si + d.y; e1 = e1 > 0.f ? e1 : ALPHA * e1;
        float e2 = si + d.z; e2 = e2 > 0.f ? e2 : ALPHA * e2;
        float e3 = si + d.w; e3 = e3 > 0.f ? e3 : ALPHA * e3;
        p[k * 4 + 0] = (av.x > 0) ? fast_exp4(e0) : 0.f;
        p[k * 4 + 1] = (av.y > 0) ? fast_exp4(e1) : 0.f;
        p[k * 4 + 2] = (av.z > 0) ? fast_exp4(e2) : 0.f;
        p[k * 4 + 3] = (av.w > 0) ? fast_exp4(e3) : 0.f;
        sum += p[k * 4 + 0] + p[k * 4 + 1] + p[k * 4 + 2] + p[k * 4 + 3];
    }
    #pragma unroll
    for (int o = 16; o; o >>= 1) sum += __shfl_xor_sync(0xffffffffu, sum, o);
    const float rinv = __frcp_rn(sum);

    __half* arow = att + ((long)bn * NODES + i) * NODES;
    #pragma unroll
    for (int k = 0; k < 4; k++) {
        __half2 h2[2];
        h2[0].x = __float2half(p[k * 4 + 0] * rinv);
        h2[0].y = __float2half(p[k * 4 + 1] * rinv);
        h2[1].x = __float2half(p[k * 4 + 2] * rinv);
        h2[1].y = __float2half(p[k * 4 + 3] * rinv);
        *(uint2*)(arow + k * 128 + lane * 4) = *(uint2*)h2;
    }
}

// ============================================================================
extern "C" void kernel_launch(void* const* d_in, const int* in_sizes, int n_in,
                              void* d_out, int out_size)
{
    const float* h   = (const float*)d_in[0];
    const int*   adj = (const int*)d_in[1];
    const float* W   = (const float*)d_in[2];
    const float* a   = (const float*)d_in[3];
    float* out = (float*)d_out;

    __half *hh, *atp, *w16, *wh;
    float *wa, *srcp, *dstp;
    cudaGetSymbolAddress((void**)&hh,  g_h16);
    cudaGetSymbolAddress((void**)&atp, g_att);
    cudaGetSymbolAddress((void**)&w16, g_W16);
    cudaGetSymbolAddress((void**)&wh,  g_Wh);
    cudaGetSymbolAddress((void**)&wa,  g_wa);
    cudaGetSymbolAddress((void**)&srcp, g_src);
    cudaGetSymbolAddress((void**)&dstp, g_dst);

    static bool init_done = false;
    static cudaStream_t s1;
    static cudaEvent_t evFork, evJoin;
    if (!init_done) {
        cudaStreamCreateWithFlags(&s1, cudaStreamNonBlocking);
        cudaEventCreateWithFlags(&evFork, cudaEventDisableTiming);
        cudaEventCreateWithFlags(&evJoin, cudaEventDisableTiming);
        cudaFuncSetAttribute(gemm1_kernel, cudaFuncAttributeMaxDynamicSharedMemorySize, G_SMEM);
        cudaFuncSetAttribute(gemm2_kernel, cudaFuncAttributeMaxDynamicSharedMemorySize, G_SMEM);
        init_done = true;
    }

    prep_w<<<64, 256>>>(W, a, w16, wa);
    conv_h<<<NB * NODES / 8, 256>>>((const float4*)h, hh, wa, srcp, dstp);

    // fork: attn on s1 concurrent with gemm1
    cudaEventRecord(evFork, 0);
    cudaStreamWaitEvent(s1, evFork, 0);
    attn_kernel<<<NB * NODES / 8, 256, 0, s1>>>(adj, srcp, dstp, atp);
    cudaEventRecord(evJoin, s1);

    {
        dim3 grid(FDIM / 64, NODES / 128, NB);
        gemm1_kernel<<<grid, 256, G_SMEM>>>(hh, w16, wh);
    }

    cudaStreamWaitEvent(0, evJoin, 0);
    {
        dim3 grid(FDIM / 64, NODES / 128, NB);
        gemm2_kernel<<<grid, 256, G_SMEM>>>(atp, wh, out);
    }
}